// round 9
// baseline (speedup 1.0000x reference)
#include <cuda_runtime.h>
#include <cstdint>
#include <math.h>

#define BATCH 8192
#define HID   1024

// ---------------- scratch (allocation-free: __device__ globals) ----------------
__device__ float g_c  [(size_t)BATCH * HID];   // c_t -> softmax a_t (in place)
__device__ float g_php[(size_t)BATCH * HID];   // relu(combined @ What.T + bhat)
__device__ float g_rh [(size_t)BATCH * HID];   // round_tf32(sigmoid(r_pre) * hidden)
__device__ float g_z  [(size_t)BATCH * HID];   // sigmoid(z_pre)
__device__ float g_u  [(size_t)BATCH * HID];   // x @ Wxh.T + bias_h

// pre-rounded (tf32-rna) operands, packed into one buffer (element offsets)
#define PX    0
#define PH    8388608
#define PWC   16777216
#define PWHAT 18874368
#define PWXR  20971520
#define PWHR  22020096
#define PWXZ  23068672
#define PWHZ  24117248
#define PWXH  25165824
#define PWHH  26214400
#define PTOT  27262976
__device__ float g_pre[PTOT];

__device__ __forceinline__ float rna_tf32(float f) {
    uint32_t u;
    asm("cvt.rna.tf32.f32 %0, %1;" : "=r"(u) : "f"(f));
    return __uint_as_float(u);
}
__device__ __forceinline__ uint32_t smem_to_u32(const void* p) {
    uint32_t a;
    asm("{ .reg .u64 tmp; cvta.to.shared.u64 tmp, %1; cvt.u32.u64 %0, tmp; }"
        : "=r"(a) : "l"(p));
    return a;
}

// ---------------- geometry ----------------
#define BM 256
#define BN 128
#define BK 32
#define SK 36                        // 32 + 4 pad words -> conflict-free LDSM (row 144B)
#define THREADS 512
#define A_ST_B  36864                // 256*36*4 bytes per A stage
#define B_ST_B  18432                // 128*36*4 bytes per B stage
#define STAGES  3
#define OFF_B_B (STAGES * A_ST_B)    // 110592
#define SMEM_BYTES (OFF_B_B + STAGES * B_ST_B)   // 165888 -> 1 CTA/SM, 16 warps

enum { M_NONE = 0, M_RELU = 1, M_SIG = 2, M_SIGMUL = 3, M_FINAL = 4 };

struct GateCfg {
    const float* A1; const float* W1;
    const float* A2; const float* W2;
    const float* bias; float* out;
    int ld1, ld2, n1, n2, mode;      // n1/n2 = #K32 chunks per phase
};
struct KParams { GateCfg g[6]; const float* hidden; };

// ---------------- pre-rounding pass (fp32 -> tf32-rna) ----------------
__global__ __launch_bounds__(256)
void preround_kernel(const float* x, const float* h, const float* wc, const float* what,
                     const float* wxr, const float* whr, const float* wxz, const float* whz,
                     const float* wxh, const float* whh)
{
    const int tid = blockIdx.x * blockDim.x + threadIdx.x;
    const int nt  = gridDim.x * blockDim.x;
    const float* srcs[10] = {x, h, wc, what, wxr, whr, wxz, whz, wxh, whh};
    float* dsts[10] = {g_pre + PX, g_pre + PH, g_pre + PWC, g_pre + PWHAT, g_pre + PWXR,
                       g_pre + PWHR, g_pre + PWXZ, g_pre + PWHZ, g_pre + PWXH, g_pre + PWHH};
    const int n4s[10] = {2097152, 2097152, 524288, 524288, 262144,
                         262144, 262144, 262144, 262144, 262144};
#pragma unroll 1
    for (int s = 0; s < 10; s++) {
        const float4* sp = (const float4*)srcs[s];
        float4*       dp = (float4*)dsts[s];
        const int n4 = n4s[s];
        for (int i = tid; i < n4; i += nt) {
            float4 v = sp[i];
            dp[i] = make_float4(rna_tf32(v.x), rna_tf32(v.y), rna_tf32(v.z), rna_tf32(v.w));
        }
    }
}

// --- tf32 mma.sync GEMM, 256x128 CTA (512 thr), 32x64 warp tile, BK=32 / 3 stages ---
__global__ __launch_bounds__(THREADS, 1)
void rau_gemm(KParams P, int gbase)
{
    extern __shared__ float smem[];
    const uint32_t su = smem_to_u32(smem);

    const GateCfg cfg = P.g[gbase + blockIdx.z];

    const int t = threadIdx.x;
    const int w = t >> 5, lane = t & 31;
    const int g = lane >> 2, tig = lane & 3;
    const int wm = w >> 1, wn = w & 1;        // 8x2 warp grid, 32x64 warp tile
    const int bm = blockIdx.y * BM;
    const int bn = blockIdx.x * BN;
    const int n1 = cfg.n1;
    const int n  = n1 + cfg.n2;

    // Per-thread cp.async slots: 4 x 16B A, 2 x 16B B per K=32 chunk.
    uint32_t baseA[4], offA[4];
    uint32_t baseB[2], oW1[2], oW2[2];
#pragma unroll
    for (int j = 0; j < 4; j++) {
        int idx = j * THREADS + t, row = idx >> 3, cg = idx & 7;
        baseA[j] = (uint32_t)(row * (SK * 4) + cg * 16);
        offA[j]  = (uint32_t)((bm + row) * HID + cg * 4);
    }
#pragma unroll
    for (int j = 0; j < 2; j++) {
        int idx = j * THREADS + t, row = idx >> 3, cg = idx & 7;
        baseB[j] = (uint32_t)(OFF_B_B + row * (SK * 4) + cg * 16);
        oW1[j]   = (uint32_t)((bn + row) * cfg.ld1 + cg * 4);
        oW2[j]   = (uint32_t)((bn + row) * cfg.ld2 + cg * 4);
    }

    // ldmatrix per-lane addresses.
    const uint32_t aAddr = su +
        (uint32_t)(((wm * 32 + ((lane >> 3) & 1) * 8 + (lane & 7)) * SK +
                    ((lane >> 4) & 1) * 4) * 4);
    const uint32_t bAddr = su + OFF_B_B +
        (uint32_t)(((wn * 64 + ((lane >> 4) & 1) * 8 + (lane & 7)) * SK +
                    ((lane >> 3) & 1) * 4) * 4);

    auto load_chunk = [&](int c, int st) {
        const bool p1 = (c < n1);
        const uint32_t kof = (uint32_t)(p1 ? c : c - n1) * 32u;
        const float* Ap = p1 ? cfg.A1 : cfg.A2;
        const float* Wp = p1 ? cfg.W1 : cfg.W2;
#pragma unroll
        for (int j = 0; j < 4; j++) {
            const float* s = Ap + offA[j] + kof;
            asm volatile("cp.async.cg.shared.global [%0], [%1], 16;\n"
                         :: "r"(su + st * A_ST_B + baseA[j]), "l"(s));
        }
#pragma unroll
        for (int j = 0; j < 2; j++) {
            const float* s = Wp + (p1 ? oW1[j] : oW2[j]) + kof;
            asm volatile("cp.async.cg.shared.global [%0], [%1], 16;\n"
                         :: "r"(su + st * B_ST_B + baseB[j]), "l"(s));
        }
    };

    float acc[2][8][4];
#pragma unroll
    for (int i = 0; i < 2; i++)
#pragma unroll
        for (int j = 0; j < 8; j++)
#pragma unroll
            for (int q = 0; q < 4; q++) acc[i][j][q] = 0.f;

    load_chunk(0, 0);
    asm volatile("cp.async.commit_group;\n" ::: "memory");
    load_chunk(1, 1);
    asm volatile("cp.async.commit_group;\n" ::: "memory");

#pragma unroll 1
    for (int i = 0; i < n; i++) {
        asm volatile("cp.async.wait_group 1;\n" ::: "memory");
        __syncthreads();
        if (i + 2 < n) {
            load_chunk(i + 2, (i + 2) % STAGES);
        }
        asm volatile("cp.async.commit_group;\n" ::: "memory");

        const int st = i % STAGES;
        const uint32_t aS = aAddr + st * A_ST_B;
        const uint32_t bS = bAddr + st * B_ST_B;

#pragma unroll
        for (int kk = 0; kk < 4; kk++) {
            uint32_t af[2][4];
#pragma unroll
            for (int ii = 0; ii < 2; ii++) {
                asm volatile("ldmatrix.sync.aligned.m8n8.x4.shared.b16 {%0,%1,%2,%3}, [%4];"
                             : "=r"(af[ii][0]), "=r"(af[ii][1]),
                               "=r"(af[ii][2]), "=r"(af[ii][3])
                             : "r"(aS + kk * 32 + ii * (16 * SK * 4)));
            }
            uint32_t bf[8][2];
#pragma unroll
            for (int jp = 0; jp < 4; jp++) {
                asm volatile("ldmatrix.sync.aligned.m8n8.x4.shared.b16 {%0,%1,%2,%3}, [%4];"
                             : "=r"(bf[jp * 2][0]),     "=r"(bf[jp * 2][1]),
                               "=r"(bf[jp * 2 + 1][0]), "=r"(bf[jp * 2 + 1][1])
                             : "r"(bS + kk * 32 + jp * (16 * SK * 4)));
            }
#pragma unroll
            for (int ii = 0; ii < 2; ii++)
#pragma unroll
                for (int jj = 0; jj < 8; jj++) {
                    asm volatile(
                        "mma.sync.aligned.m16n8k8.row.col.f32.tf32.tf32.f32 "
                        "{%0,%1,%2,%3},{%4,%5,%6,%7},{%8,%9},{%0,%1,%2,%3};\n"
                        : "+f"(acc[ii][jj][0]), "+f"(acc[ii][jj][1]),
                          "+f"(acc[ii][jj][2]), "+f"(acc[ii][jj][3])
                        : "r"(af[ii][0]), "r"(af[ii][1]), "r"(af[ii][2]), "r"(af[ii][3]),
                          "r"(bf[jj][0]), "r"(bf[jj][1]));
                }
        }
    }

    // ---------------- fused epilogue ----------------
    const int mode = cfg.mode;
    float* out = cfg.out;
    const float* bias = cfg.bias;
    const float* hid = P.hidden;

#pragma unroll
    for (int ii = 0; ii < 2; ii++) {
#pragma unroll
        for (int jj = 0; jj < 8; jj++) {
            const int r0  = bm + wm * 32 + ii * 16 + g;
            const int col = bn + wn * 64 + jj * 8 + 2 * tig;
            float b0 = 0.f, b1 = 0.f;
            if (bias) { b0 = bias[col]; b1 = bias[col + 1]; }
#pragma unroll
            for (int hrow = 0; hrow < 2; hrow++) {
                const size_t idx = (size_t)(r0 + hrow * 8) * HID + col;
                float v0 = acc[ii][jj][hrow * 2    ] + b0;
                float v1 = acc[ii][jj][hrow * 2 + 1] + b1;
                float2 res;
                if (mode == M_NONE) {
                    res = make_float2(v0, v1);
                } else if (mode == M_RELU) {
                    res = make_float2(fmaxf(v0, 0.f), fmaxf(v1, 0.f));
                } else if (mode == M_SIG) {
                    res = make_float2(1.f / (1.f + __expf(-v0)),
                                      1.f / (1.f + __expf(-v1)));
                } else if (mode == M_SIGMUL) {
                    float2 h2 = *(const float2*)(hid + idx);
                    res = make_float2(rna_tf32(h2.x / (1.f + __expf(-v0))),
                                      rna_tf32(h2.y / (1.f + __expf(-v1))));
                } else { // M_FINAL
                    float2 u2 = *(const float2*)(g_u   + idx);
                    float2 z2 = *(const float2*)(g_z   + idx);
                    float2 a2 = *(const float2*)(g_c   + idx);
                    float2 p2 = *(const float2*)(g_php + idx);
                    float2 h2 = *(const float2*)(hid   + idx);
                    float t0 = tanhf(u2.x + v0), t1 = tanhf(u2.y + v1);
                    res = make_float2((1.f - z2.x) * t0 + z2.x * h2.x + a2.x * p2.x,
                                      (1.f - z2.y) * t1 + z2.y * h2.y + a2.y * p2.y);
                }
                *(float2*)(out + idx) = res;
            }
        }
    }
}

// ---------------- row softmax over g_c in place ----------------
__global__ __launch_bounds__(256)
void softmax_kernel()
{
    const int row = blockIdx.x;
    float* p = g_c + (size_t)row * HID;
    const int tid = threadIdx.x;

    float4 v = reinterpret_cast<float4*>(p)[tid];
    float m = fmaxf(fmaxf(v.x, v.y), fmaxf(v.z, v.w));
#pragma unroll
    for (int o = 16; o; o >>= 1) m = fmaxf(m, __shfl_xor_sync(~0u, m, o));

    __shared__ float smax[8];
    __shared__ float ssum[8];
    if ((tid & 31) == 0) smax[tid >> 5] = m;
    __syncthreads();
    float M = -1e30f;
#pragma unroll
    for (int i = 0; i < 8; i++) M = fmaxf(M, smax[i]);

    float e0 = expf(v.x - M), e1 = expf(v.y - M), e2 = expf(v.z - M), e3 = expf(v.w - M);
    float s = e0 + e1 + e2 + e3;
#pragma unroll
    for (int o = 16; o; o >>= 1) s += __shfl_xor_sync(~0u, s, o);
    if ((tid & 31) == 0) ssum[tid >> 5] = s;
    __syncthreads();
    float S = 0.f;
#pragma unroll
    for (int i = 0; i < 8; i++) S += ssum[i];
    float inv = 1.f / S;

    reinterpret_cast<float4*>(p)[tid] = make_float4(e0 * inv, e1 * inv, e2 * inv, e3 * inv);
}

// ---------------- launch ----------------
extern "C" void kernel_launch(void* const* d_in, const int* in_sizes, int n_in,
                              void* d_out, int out_size)
{
    const float* x    = (const float*)d_in[0];
    const float* h    = (const float*)d_in[1];
    const float* wxr  = (const float*)d_in[2];
    const float* whr  = (const float*)d_in[3];
    const float* br   = (const float*)d_in[4];
    const float* wxz  = (const float*)d_in[5];
    const float* whz  = (const float*)d_in[6];
    const float* bz   = (const float*)d_in[7];
    const float* wxh  = (const float*)d_in[8];
    const float* whh  = (const float*)d_in[9];
    const float* bh   = (const float*)d_in[10];
    const float* wc   = (const float*)d_in[11];
    const float* bc   = (const float*)d_in[12];
    const float* what = (const float*)d_in[13];
    const float* bhat = (const float*)d_in[14];

    float *pre, *pc, *pphp, *prh, *pz, *pu;
    cudaGetSymbolAddress((void**)&pre,  g_pre);
    cudaGetSymbolAddress((void**)&pc,   g_c);
    cudaGetSymbolAddress((void**)&pphp, g_php);
    cudaGetSymbolAddress((void**)&prh,  g_rh);
    cudaGetSymbolAddress((void**)&pz,   g_z);
    cudaGetSymbolAddress((void**)&pu,   g_u);

    KParams P;
    P.hidden = h;
    P.g[0] = {pre + PX, pre + PWC,   pre + PH, pre + PWC + 1024,   bc,   pc,   2048, 2048, 32, 32, M_NONE};
    P.g[1] = {pre + PX, pre + PWHAT, pre + PH, pre + PWHAT + 1024, bhat, pphp, 2048, 2048, 32, 32, M_RELU};
    P.g[2] = {pre + PX, pre + PWXR,  pre + PH, pre + PWHR,         br,   prh,  1024, 1024, 32, 32, M_SIGMUL};
    P.g[3] = {pre + PX, pre + PWXZ,  pre + PH, pre + PWHZ,         bz,   pz,   1024, 1024, 32, 32, M_SIG};
    P.g[4] = {pre + PX, pre + PWXH,  nullptr,  nullptr,            bh,   pu,   1024, 1024, 32, 0,  M_NONE};
    P.g[5] = {prh,      pre + PWHH,  nullptr,  nullptr,            nullptr, (float*)d_out, 1024, 1024, 32, 0, M_FINAL};

    cudaFuncSetAttribute(rau_gemm, cudaFuncAttributeMaxDynamicSharedMemorySize, SMEM_BYTES);

    preround_kernel<<<1024, 256>>>(x, h, wc, what, wxr, whr, wxz, whz, wxh, whh);

    // 5 independent projections batched in one launch (blockIdx.z selects gate)
    rau_gemm<<<dim3(HID / BN, BATCH / BM, 5), THREADS, SMEM_BYTES>>>(P, 0);

    // a = softmax(c) in place
    softmax_kernel<<<BATCH, 256>>>();

    // h_t = (1-z)*tanh(u + rh@Whh.T) + z*h + a*php
    rau_gemm<<<dim3(HID / BN, BATCH / BM, 1), THREADS, SMEM_BYTES>>>(P, 5);
}

// round 10
// speedup vs baseline: 1.1849x; 1.1849x over previous
#include <cuda_runtime.h>
#include <cstdint>
#include <math.h>

#define BATCH 8192
#define HID   1024

// ---------------- scratch (allocation-free: __device__ globals) ----------------
__device__ float g_c  [(size_t)BATCH * HID];   // c_t (raw pre-softmax logits)
__device__ float g_php[(size_t)BATCH * HID];   // relu(combined @ What.T + bhat)
__device__ float g_rh [(size_t)BATCH * HID];   // sigmoid(r_pre) * hidden
__device__ float g_z  [(size_t)BATCH * HID];   // sigmoid(z_pre)
__device__ float g_u  [(size_t)BATCH * HID];   // x @ Wxh.T + bias_h
__device__ float g_rowM   [BATCH];             // row max of c
__device__ float g_rowInvS[BATCH];             // 1 / sum(exp(c - M))

__device__ __forceinline__ uint32_t smem_to_u32(const void* p) {
    uint32_t a;
    asm("{ .reg .u64 tmp; cvta.to.shared.u64 tmp, %1; cvt.u32.u64 %0, tmp; }"
        : "=r"(a) : "l"(p));
    return a;
}

// ---------------- geometry ----------------
#define BM 128
#define BN 128
#define BK 32
#define SK 36                        // 32 + 4 pad words -> conflict-free LDSM (row 144B)
#define A_ST_B  18432                // 128*36*4 bytes per A stage
#define B_ST_B  18432
#define STAGES  3
#define OFF_B_B (STAGES * A_ST_B)    // 55296
#define SMEM_BYTES (OFF_B_B + STAGES * B_ST_B)   // 110592 -> 2 CTAs/SM

enum { M_NONE = 0, M_RELU = 1, M_SIG = 2, M_SIGMUL = 3, M_FINAL = 4 };

struct GateCfg {
    const float* A1; const float* W1;
    const float* A2; const float* W2;
    const float* bias; float* out;
    int ld1, ld2, n1, n2, mode;      // n1/n2 = #K32 chunks per phase
};
struct KParams { GateCfg g[6]; const float* hidden; };

// --- tf32 mma.sync GEMM, 128x128 CTA, 32x64 warp tile, BK=32 / 3 stages, 2 CTAs/SM ---
// fp32 operands fed directly; HMMA truncates to tf32 (RZ) in hardware.
__global__ __launch_bounds__(256, 2)
void rau_gemm(KParams P, int gbase)
{
    extern __shared__ float smem[];
    const uint32_t su = smem_to_u32(smem);

    const GateCfg cfg = P.g[gbase + blockIdx.z];

    const int t = threadIdx.x;
    const int w = t >> 5, lane = t & 31;
    const int g = lane >> 2, tig = lane & 3;
    const int wm = w >> 1, wn = w & 1;        // 4x2 warp grid, 32x64 warp tile
    const int bm = blockIdx.y * BM;
    const int bn = blockIdx.x * BN;
    const int n1 = cfg.n1;
    const int n  = n1 + cfg.n2;

    // Per-thread cp.async slots: 4 x 16B A, 4 x 16B B per K=32 chunk.
    uint32_t baseA[4], offA[4];
    uint32_t baseB[4], oW1[4], oW2[4];
#pragma unroll
    for (int j = 0; j < 4; j++) {
        int idx = j * 256 + t, row = idx >> 3, cg = idx & 7;
        baseA[j] = (uint32_t)(row * (SK * 4) + cg * 16);
        offA[j]  = (uint32_t)((bm + row) * HID + cg * 4);
        baseB[j] = (uint32_t)(OFF_B_B + row * (SK * 4) + cg * 16);
        oW1[j]   = (uint32_t)((bn + row) * cfg.ld1 + cg * 4);
        oW2[j]   = (uint32_t)((bn + row) * cfg.ld2 + cg * 4);
    }

    // ldmatrix per-lane addresses.
    const uint32_t aAddr = su +
        (uint32_t)(((wm * 32 + ((lane >> 3) & 1) * 8 + (lane & 7)) * SK +
                    ((lane >> 4) & 1) * 4) * 4);
    const uint32_t bAddr = su + OFF_B_B +
        (uint32_t)(((wn * 64 + ((lane >> 4) & 1) * 8 + (lane & 7)) * SK +
                    ((lane >> 3) & 1) * 4) * 4);

    auto load_chunk = [&](int c, int st) {
        const bool p1 = (c < n1);
        const uint32_t kof = (uint32_t)(p1 ? c : c - n1) * 32u;
        const float* Ap = p1 ? cfg.A1 : cfg.A2;
        const float* Wp = p1 ? cfg.W1 : cfg.W2;
#pragma unroll
        for (int j = 0; j < 4; j++) {
            const float* s = Ap + offA[j] + kof;
            asm volatile("cp.async.cg.shared.global [%0], [%1], 16;\n"
                         :: "r"(su + st * A_ST_B + baseA[j]), "l"(s));
        }
#pragma unroll
        for (int j = 0; j < 4; j++) {
            const float* s = Wp + (p1 ? oW1[j] : oW2[j]) + kof;
            asm volatile("cp.async.cg.shared.global [%0], [%1], 16;\n"
                         :: "r"(su + st * B_ST_B + baseB[j]), "l"(s));
        }
    };

    float acc[2][8][4];
#pragma unroll
    for (int i = 0; i < 2; i++)
#pragma unroll
        for (int j = 0; j < 8; j++)
#pragma unroll
            for (int q = 0; q < 4; q++) acc[i][j][q] = 0.f;

    load_chunk(0, 0);
    asm volatile("cp.async.commit_group;\n" ::: "memory");
    load_chunk(1, 1);
    asm volatile("cp.async.commit_group;\n" ::: "memory");

#pragma unroll 1
    for (int i = 0; i < n; i++) {
        asm volatile("cp.async.wait_group 1;\n" ::: "memory");
        __syncthreads();
        if (i + 2 < n) {
            load_chunk(i + 2, (i + 2) % STAGES);
        }
        asm volatile("cp.async.commit_group;\n" ::: "memory");

        const int st = i % STAGES;
        const uint32_t aS = aAddr + st * A_ST_B;
        const uint32_t bS = bAddr + st * B_ST_B;

#pragma unroll
        for (int kk = 0; kk < 4; kk++) {
            uint32_t af[2][4];
#pragma unroll
            for (int ii = 0; ii < 2; ii++) {
                asm volatile("ldmatrix.sync.aligned.m8n8.x4.shared.b16 {%0,%1,%2,%3}, [%4];"
                             : "=r"(af[ii][0]), "=r"(af[ii][1]),
                               "=r"(af[ii][2]), "=r"(af[ii][3])
                             : "r"(aS + kk * 32 + ii * (16 * SK * 4)));
            }
            uint32_t bf[8][2];
#pragma unroll
            for (int jp = 0; jp < 4; jp++) {
                asm volatile("ldmatrix.sync.aligned.m8n8.x4.shared.b16 {%0,%1,%2,%3}, [%4];"
                             : "=r"(bf[jp * 2][0]),     "=r"(bf[jp * 2][1]),
                               "=r"(bf[jp * 2 + 1][0]), "=r"(bf[jp * 2 + 1][1])
                             : "r"(bS + kk * 32 + jp * (16 * SK * 4)));
            }
#pragma unroll
            for (int ii = 0; ii < 2; ii++)
#pragma unroll
                for (int jj = 0; jj < 8; jj++) {
                    asm volatile(
                        "mma.sync.aligned.m16n8k8.row.col.f32.tf32.tf32.f32 "
                        "{%0,%1,%2,%3},{%4,%5,%6,%7},{%8,%9},{%0,%1,%2,%3};\n"
                        : "+f"(acc[ii][jj][0]), "+f"(acc[ii][jj][1]),
                          "+f"(acc[ii][jj][2]), "+f"(acc[ii][jj][3])
                        : "r"(af[ii][0]), "r"(af[ii][1]), "r"(af[ii][2]), "r"(af[ii][3]),
                          "r"(bf[jj][0]), "r"(bf[jj][1]));
                }
        }
    }

    // ---------------- fused epilogue ----------------
    const int mode = cfg.mode;
    float* out = cfg.out;
    const float* bias = cfg.bias;
    const float* hid = P.hidden;

#pragma unroll
    for (int ii = 0; ii < 2; ii++) {
#pragma unroll
        for (int jj = 0; jj < 8; jj++) {
            const int r0  = bm + wm * 32 + ii * 16 + g;
            const int col = bn + wn * 64 + jj * 8 + 2 * tig;
            float b0 = 0.f, b1 = 0.f;
            if (bias) { b0 = bias[col]; b1 = bias[col + 1]; }
#pragma unroll
            for (int hrow = 0; hrow < 2; hrow++) {
                const int rowi = r0 + hrow * 8;
                const size_t idx = (size_t)rowi * HID + col;
                float v0 = acc[ii][jj][hrow * 2    ] + b0;
                float v1 = acc[ii][jj][hrow * 2 + 1] + b1;
                float2 res;
                if (mode == M_NONE) {
                    res = make_float2(v0, v1);
                } else if (mode == M_RELU) {
                    res = make_float2(fmaxf(v0, 0.f), fmaxf(v1, 0.f));
                } else if (mode == M_SIG) {
                    res = make_float2(1.f / (1.f + __expf(-v0)),
                                      1.f / (1.f + __expf(-v1)));
                } else if (mode == M_SIGMUL) {
                    float2 h2 = *(const float2*)(hid + idx);
                    res = make_float2(h2.x / (1.f + __expf(-v0)),
                                      h2.y / (1.f + __expf(-v1)));
                } else { // M_FINAL
                    float2 u2 = *(const float2*)(g_u   + idx);
                    float2 z2 = *(const float2*)(g_z   + idx);
                    float2 c2 = *(const float2*)(g_c   + idx);
                    float2 p2 = *(const float2*)(g_php + idx);
                    float2 h2 = *(const float2*)(hid   + idx);
                    const float M  = g_rowM[rowi];
                    const float iS = g_rowInvS[rowi];
                    float a0 = expf(c2.x - M) * iS;
                    float a1 = expf(c2.y - M) * iS;
                    float t0 = tanhf(u2.x + v0), t1 = tanhf(u2.y + v1);
                    res = make_float2((1.f - z2.x) * t0 + z2.x * h2.x + a0 * p2.x,
                                      (1.f - z2.y) * t1 + z2.y * h2.y + a1 * p2.y);
                }
                *(float2*)(out + idx) = res;
            }
        }
    }
}

// ---------------- per-row softmax stats over g_c (one warp per row) ----------------
__global__ __launch_bounds__(256)
void rowstat_kernel()
{
    const int row  = (blockIdx.x * blockDim.x + threadIdx.x) >> 5;
    const int lane = threadIdx.x & 31;
    const float4* p = (const float4*)(g_c + (size_t)row * HID);

    float4 v[8];
    float m = -1e30f;
#pragma unroll
    for (int i = 0; i < 8; i++) {
        v[i] = p[i * 32 + lane];
        m = fmaxf(m, fmaxf(fmaxf(v[i].x, v[i].y), fmaxf(v[i].z, v[i].w)));
    }
#pragma unroll
    for (int o = 16; o; o >>= 1) m = fmaxf(m, __shfl_xor_sync(~0u, m, o));

    float s = 0.f;
#pragma unroll
    for (int i = 0; i < 8; i++) {
        s += expf(v[i].x - m) + expf(v[i].y - m) + expf(v[i].z - m) + expf(v[i].w - m);
    }
#pragma unroll
    for (int o = 16; o; o >>= 1) s += __shfl_xor_sync(~0u, s, o);

    if (lane == 0) {
        g_rowM[row]    = m;
        g_rowInvS[row] = 1.f / s;
    }
}

// ---------------- launch ----------------
extern "C" void kernel_launch(void* const* d_in, const int* in_sizes, int n_in,
                              void* d_out, int out_size)
{
    const float* x    = (const float*)d_in[0];
    const float* h    = (const float*)d_in[1];
    const float* wxr  = (const float*)d_in[2];
    const float* whr  = (const float*)d_in[3];
    const float* br   = (const float*)d_in[4];
    const float* wxz  = (const float*)d_in[5];
    const float* whz  = (const float*)d_in[6];
    const float* bz   = (const float*)d_in[7];
    const float* wxh  = (const float*)d_in[8];
    const float* whh  = (const float*)d_in[9];
    const float* bh   = (const float*)d_in[10];
    const float* wc   = (const float*)d_in[11];
    const float* bc   = (const float*)d_in[12];
    const float* what = (const float*)d_in[13];
    const float* bhat = (const float*)d_in[14];

    float *pc, *pphp, *prh, *pz, *pu;
    cudaGetSymbolAddress((void**)&pc,   g_c);
    cudaGetSymbolAddress((void**)&pphp, g_php);
    cudaGetSymbolAddress((void**)&prh,  g_rh);
    cudaGetSymbolAddress((void**)&pz,   g_z);
    cudaGetSymbolAddress((void**)&pu,   g_u);

    KParams P;
    P.hidden = h;
    P.g[0] = {x,   wc,   h, wc + 1024,   bc,   pc,   2048, 2048, 32, 32, M_NONE};
    P.g[1] = {x,   what, h, what + 1024, bhat, pphp, 2048, 2048, 32, 32, M_RELU};
    P.g[2] = {x,   wxr,  h, whr,         br,   prh,  1024, 1024, 32, 32, M_SIGMUL};
    P.g[3] = {x,   wxz,  h, whz,         bz,   pz,   1024, 1024, 32, 32, M_SIG};
    P.g[4] = {x,   wxh,  nullptr, nullptr, bh, pu,   1024, 1024, 32, 0,  M_NONE};
    P.g[5] = {prh, whh,  nullptr, nullptr, nullptr, (float*)d_out, 1024, 1024, 32, 0, M_FINAL};

    cudaFuncSetAttribute(rau_gemm, cudaFuncAttributeMaxDynamicSharedMemorySize, SMEM_BYTES);

    // 5 independent projections batched in one launch (blockIdx.z selects gate)
    rau_gemm<<<dim3(HID / BN, BATCH / BM, 5), 256, SMEM_BYTES>>>(P, 0);

    // per-row softmax stats of c
    rowstat_kernel<<<BATCH / 8, 256>>>();

    // h_t = (1-z)*tanh(u + rh@Whh.T) + z*h + softmax(c)*php
    rau_gemm<<<dim3(HID / BN, BATCH / BM, 1), 256, SMEM_BYTES>>>(P, 5);
}